// round 5
// baseline (speedup 1.0000x reference)
#include <cuda_runtime.h>
#include <cuda_fp16.h>
#include <stdint.h>

// out[num_rows, 128] = segment_sum(W[cols]*vals, rows) + b
//
// R4: row_gather is now issue/latency-bound (issue=54.8%, L2=34%).
// Restructure: direct broadcast LDG.128 slot reads (2 nnz per load, no shfl),
// two independent FMA accumulator chains, precomputed per-lane W addressing.
// Aux: merge zero+convert kernels; persistent-loop overflow fixup.

static constexpr int UNITS    = 128;
static constexpr int WCOLS    = 8192;
static constexpr int SLOTS    = 48;
static constexpr int MAX_ROWS = 1 << 17;
static constexpr int OVF_CAP  = 65536;

__device__ __half g_Wh[WCOLS * UNITS];               // 2 MB fp16 W
__device__ int    g_cnt[MAX_ROWS];
__device__ float2 g_slot[(size_t)MAX_ROWS * SLOTS];  // (val, bitcast(col))
__device__ float4 g_ovf[OVF_CAP];                    // (val, col, row, -)
__device__ int    g_ovf_n;

// ---- k0: zero counters + convert W -> fp16 (merged) ----
__global__ void prep_kernel(const float* __restrict__ W, int n4, int num_rows) {
    int i = blockIdx.x * blockDim.x + threadIdx.x;
    if (i < num_rows) g_cnt[i] = 0;
    if (i == 0) g_ovf_n = 0;
    if (i < n4) {
        float4 f = __ldg(reinterpret_cast<const float4*>(W) + i);
        __half2 h0 = __floats2half2_rn(f.x, f.y);
        __half2 h1 = __floats2half2_rn(f.z, f.w);
        uint2 u;
        u.x = *reinterpret_cast<uint32_t*>(&h0);
        u.y = *reinterpret_cast<uint32_t*>(&h1);
        reinterpret_cast<uint2*>(g_Wh)[i] = u;
    }
}

// ---- k1: scatter nonzeros into per-row slots ----
__global__ void scatter_bins_kernel(const float* __restrict__ vals,
                                    const int* __restrict__ rows,
                                    const int* __restrict__ cols,
                                    int nnz) {
    int i = blockIdx.x * blockDim.x + threadIdx.x;
    if (i >= nnz) return;
    int   r = rows[i];
    float v = vals[i];
    int   c = cols[i];
    int pos = atomicAdd(&g_cnt[r], 1);
    if (pos < SLOTS) {
        g_slot[(size_t)r * SLOTS + pos] = make_float2(v, __int_as_float(c));
    } else {
        int op = atomicAdd(&g_ovf_n, 1);
        if (op < OVF_CAP)
            g_ovf[op] = make_float4(v, __int_as_float(c), __int_as_float(r), 0.f);
    }
}

// ---- k2: warp per row: gather fp16 W, dual fp32 accum chains, one store ----
__global__ void __launch_bounds__(256) row_gather_kernel(
        const float* __restrict__ b,
        float* __restrict__ out,
        int num_rows) {
    int warp = (blockIdx.x * blockDim.x + threadIdx.x) >> 5;
    int lane = threadIdx.x & 31;
    if (warp >= num_rows) return;

    int cnt = g_cnt[warp];
    if (cnt > SLOTS) cnt = SLOTS;

    // Per-lane W base: 4 halfs (8 bytes) per lane; W row = 256 bytes.
    const char* Wl = reinterpret_cast<const char*>(g_Wh) + lane * 8;
    const float2* slots = g_slot + (size_t)warp * SLOTS;

    float4 acc0 = make_float4(0.f, 0.f, 0.f, 0.f);
    float4 acc1 = make_float4(0.f, 0.f, 0.f, 0.f);

    int j = 0;
    int pairs = cnt >> 1;
    #pragma unroll 4
    for (int p = 0; p < pairs; ++p, j += 2) {
        // One broadcast LDG.128 fetches two nonzeros' metadata.
        float4 s = __ldg(reinterpret_cast<const float4*>(slots + j));
        float v0 = s.x; size_t c0 = (size_t)(uint32_t)__float_as_int(s.y);
        float v1 = s.z; size_t c1 = (size_t)(uint32_t)__float_as_int(s.w);

        uint2 u0 = __ldg(reinterpret_cast<const uint2*>(Wl + (c0 << 8)));
        uint2 u1 = __ldg(reinterpret_cast<const uint2*>(Wl + (c1 << 8)));

        float2 a0 = __half22float2(*reinterpret_cast<__half2*>(&u0.x));
        float2 b0 = __half22float2(*reinterpret_cast<__half2*>(&u0.y));
        acc0.x = fmaf(a0.x, v0, acc0.x);
        acc0.y = fmaf(a0.y, v0, acc0.y);
        acc0.z = fmaf(b0.x, v0, acc0.z);
        acc0.w = fmaf(b0.y, v0, acc0.w);

        float2 a1 = __half22float2(*reinterpret_cast<__half2*>(&u1.x));
        float2 b1 = __half22float2(*reinterpret_cast<__half2*>(&u1.y));
        acc1.x = fmaf(a1.x, v1, acc1.x);
        acc1.y = fmaf(a1.y, v1, acc1.y);
        acc1.z = fmaf(b1.x, v1, acc1.z);
        acc1.w = fmaf(b1.y, v1, acc1.w);
    }
    if (j < cnt) {  // odd leftover
        float2 s = __ldg(slots + j);
        float v0 = s.x; size_t c0 = (size_t)(uint32_t)__float_as_int(s.y);
        uint2 u0 = __ldg(reinterpret_cast<const uint2*>(Wl + (c0 << 8)));
        float2 a0 = __half22float2(*reinterpret_cast<__half2*>(&u0.x));
        float2 b0 = __half22float2(*reinterpret_cast<__half2*>(&u0.y));
        acc0.x = fmaf(a0.x, v0, acc0.x);
        acc0.y = fmaf(a0.y, v0, acc0.y);
        acc0.z = fmaf(b0.x, v0, acc0.z);
        acc0.w = fmaf(b0.y, v0, acc0.w);
    }

    float4 bias = __ldg(reinterpret_cast<const float4*>(b) + lane);
    acc0.x += acc1.x + bias.x;
    acc0.y += acc1.y + bias.y;
    acc0.z += acc1.z + bias.z;
    acc0.w += acc1.w + bias.w;
    reinterpret_cast<float4*>(out)[(size_t)warp * (UNITS / 4) + lane] = acc0;
}

// ---- k3: overflow fixup, persistent loop (expected empty) ----
__global__ void overflow_fix_kernel(const float* __restrict__ W,
                                    float* __restrict__ out) {
    int n = g_ovf_n;
    if (n > OVF_CAP) n = OVF_CAP;
    int warps_total = (gridDim.x * blockDim.x) >> 5;
    int warp = (blockIdx.x * blockDim.x + threadIdx.x) >> 5;
    int lane = threadIdx.x & 31;
    for (int e = warp; e < n; e += warps_total) {
        float4 ent = g_ovf[e];
        float v = ent.x;
        size_t c = (size_t)(uint32_t)__float_as_int(ent.y);
        size_t r = (size_t)(uint32_t)__float_as_int(ent.z);
        float4 w = __ldg(reinterpret_cast<const float4*>(W) + c * 32 + lane);
        float4 p;
        p.x = w.x * v; p.y = w.y * v; p.z = w.z * v; p.w = w.w * v;
        float* dst = out + r * UNITS + lane * 4;
        asm volatile("red.global.add.v4.f32 [%0], {%1, %2, %3, %4};"
                     :: "l"(dst), "f"(p.x), "f"(p.y), "f"(p.z), "f"(p.w)
                     : "memory");
    }
}

extern "C" void kernel_launch(void* const* d_in, const int* in_sizes, int n_in,
                              void* d_out, int out_size) {
    const float* vals = (const float*)d_in[0];
    const int*   rows = (const int*)d_in[1];
    const int*   cols = (const int*)d_in[2];
    const float* W    = (const float*)d_in[3];
    const float* b    = (const float*)d_in[4];
    float* out = (float*)d_out;

    int nnz = in_sizes[0];
    int num_rows = out_size / UNITS;

    const int T = 256;
    int n4 = WCOLS * UNITS / 4;   // 262144 >= num_rows, covers both ranges

    prep_kernel<<<(n4 + T - 1) / T, T>>>(W, n4, num_rows);
    scatter_bins_kernel<<<(nnz + T - 1) / T, T>>>(vals, rows, cols, nnz);
    int gblocks = (int)(((long)num_rows * 32 + T - 1) / T);
    row_gather_kernel<<<gblocks, T>>>(b, out, num_rows);
    overflow_fix_kernel<<<64, T>>>(W, out);
}

// round 6
// speedup vs baseline: 1.2364x; 1.2364x over previous
#include <cuda_runtime.h>
#include <cuda_fp16.h>
#include <stdint.h>

// out[num_rows, 128] = segment_sum(W[cols]*vals, rows) + b
//
// R5: revert R4's broadcast-slot-load regression; keep R3's coalesced
// metadata + shfl scheme. New: half-warp split (2 nnz per inner iteration,
// each lane covers 8 units via one LDG.128 of fp16 W), launch fusion
// (convert-W merged into scatter; overflow fixup inlined into row_gather).

static constexpr int UNITS    = 128;
static constexpr int WCOLS    = 8192;
static constexpr int SLOTS    = 48;
static constexpr int MAX_ROWS = 1 << 17;
static constexpr int OVF_CAP  = 65536;

__device__ __align__(16) __half g_Wh[WCOLS * UNITS];  // 2 MB fp16 W
__device__ int    g_cnt[MAX_ROWS];
__device__ float2 g_slot[(size_t)MAX_ROWS * SLOTS];   // (val, bitcast(col))
__device__ float4 g_ovf[OVF_CAP];                     // (val, col, row, -)
__device__ int    g_ovf_n;

// ---- k0: zero per-row counters + overflow counter ----
__global__ void zero_kernel(int num_rows) {
    int i = blockIdx.x * blockDim.x + threadIdx.x;
    if (i < num_rows) g_cnt[i] = 0;
    if (i == 0) g_ovf_n = 0;
}

// ---- k1: scatter nonzeros into per-row slots + convert W -> fp16 ----
__global__ void scatter_convert_kernel(const float* __restrict__ vals,
                                       const int* __restrict__ rows,
                                       const int* __restrict__ cols,
                                       const float* __restrict__ W,
                                       int nnz, int n4) {
    int i = blockIdx.x * blockDim.x + threadIdx.x;

    if (i < n4) {  // W conversion rides along on the first 262144 threads
        float4 f = __ldg(reinterpret_cast<const float4*>(W) + i);
        __half2 h0 = __floats2half2_rn(f.x, f.y);
        __half2 h1 = __floats2half2_rn(f.z, f.w);
        uint2 u;
        u.x = *reinterpret_cast<uint32_t*>(&h0);
        u.y = *reinterpret_cast<uint32_t*>(&h1);
        reinterpret_cast<uint2*>(g_Wh)[i] = u;
    }

    if (i < nnz) {
        int   r = rows[i];
        float v = vals[i];
        int   c = cols[i];
        int pos = atomicAdd(&g_cnt[r], 1);
        if (pos < SLOTS) {
            g_slot[(size_t)r * SLOTS + pos] = make_float2(v, __int_as_float(c));
        } else {
            int op = atomicAdd(&g_ovf_n, 1);
            if (op < OVF_CAP)
                g_ovf[op] = make_float4(v, __int_as_float(c), __int_as_float(r), 0.f);
        }
    }
}

// ---- k2: warp per row; half-warp split: lanes 0-15 even nnz, 16-31 odd ----
__global__ void __launch_bounds__(256) row_gather_kernel(
        const float* __restrict__ b,
        float* __restrict__ out,
        int num_rows) {
    int warp = (blockIdx.x * blockDim.x + threadIdx.x) >> 5;
    int lane = threadIdx.x & 31;
    if (warp >= num_rows) return;

    int hi  = lane >> 4;        // which nonzero of the pair this lane serves
    int sub = lane & 15;        // covers units [8*sub, 8*sub+8)

    int cnt = g_cnt[warp];
    if (cnt > SLOTS) cnt = SLOTS;

    const char* Wl = reinterpret_cast<const char*>(g_Wh) + sub * 16;
    const float2* slots = g_slot + (size_t)warp * SLOTS;

    float4 accA = make_float4(0.f, 0.f, 0.f, 0.f);  // units [8s, 8s+4)
    float4 accB = make_float4(0.f, 0.f, 0.f, 0.f);  // units [8s+4, 8s+8)

    for (int k = 0; k < cnt; k += 32) {
        int m = cnt - k;
        if (m > 32) m = 32;
        // Coalesced metadata load: lane i owns nonzero k+i; v=0 past end.
        float v = 0.f;
        int   c = 0;
        if (lane < m) {
            float2 p = __ldg(slots + k + lane);
            v = p.x;
            c = __float_as_int(p.y);
        }

        int iters = (m + 1) >> 1;
        #pragma unroll 4
        for (int p = 0; p < iters; ++p) {
            int j  = 2 * p + hi;                          // <= 31 always
            float vj = __shfl_sync(0xffffffffu, v, j);    // 0 if j >= m
            int   cj = __shfl_sync(0xffffffffu, c, j);

            uint4 u = __ldg(reinterpret_cast<const uint4*>(
                          Wl + ((size_t)(uint32_t)cj << 8)));
            float2 f0 = __half22float2(*reinterpret_cast<__half2*>(&u.x));
            float2 f1 = __half22float2(*reinterpret_cast<__half2*>(&u.y));
            float2 f2 = __half22float2(*reinterpret_cast<__half2*>(&u.z));
            float2 f3 = __half22float2(*reinterpret_cast<__half2*>(&u.w));
            accA.x = fmaf(f0.x, vj, accA.x);
            accA.y = fmaf(f0.y, vj, accA.y);
            accA.z = fmaf(f1.x, vj, accA.z);
            accA.w = fmaf(f1.y, vj, accA.w);
            accB.x = fmaf(f2.x, vj, accB.x);
            accB.y = fmaf(f2.y, vj, accB.y);
            accB.z = fmaf(f3.x, vj, accB.z);
            accB.w = fmaf(f3.y, vj, accB.w);
        }
    }

    // Combine even/odd half-warp partials (both halves end up with the sum).
    accA.x += __shfl_xor_sync(0xffffffffu, accA.x, 16);
    accA.y += __shfl_xor_sync(0xffffffffu, accA.y, 16);
    accA.z += __shfl_xor_sync(0xffffffffu, accA.z, 16);
    accA.w += __shfl_xor_sync(0xffffffffu, accA.w, 16);
    accB.x += __shfl_xor_sync(0xffffffffu, accB.x, 16);
    accB.y += __shfl_xor_sync(0xffffffffu, accB.y, 16);
    accB.z += __shfl_xor_sync(0xffffffffu, accB.z, 16);
    accB.w += __shfl_xor_sync(0xffffffffu, accB.w, 16);

    // Each lane stores one float4: unit base = 8*sub + 4*hi.
    int ubase = sub * 8 + hi * 4;
    float4 r = hi ? accB : accA;

    // Inline overflow fixup (expected empty): owner warp applies matching
    // overflow entries to its own row -> no cross-kernel RMW race.
    int ovn = g_ovf_n;
    if (ovn > 0) {
        if (ovn > OVF_CAP) ovn = OVF_CAP;
        for (int e = 0; e < ovn; ++e) {
            float4 ent = g_ovf[e];
            if (__float_as_int(ent.z) == warp) {
                float ve = ent.x;
                size_t ce = (size_t)(uint32_t)__float_as_int(ent.y);
                uint2 u = __ldg(reinterpret_cast<const uint2*>(
                              g_Wh + ce * UNITS + ubase));
                float2 e0 = __half22float2(*reinterpret_cast<__half2*>(&u.x));
                float2 e1 = __half22float2(*reinterpret_cast<__half2*>(&u.y));
                r.x = fmaf(e0.x, ve, r.x);
                r.y = fmaf(e0.y, ve, r.y);
                r.z = fmaf(e1.x, ve, r.z);
                r.w = fmaf(e1.y, ve, r.w);
            }
        }
    }

    float4 bias = __ldg(reinterpret_cast<const float4*>(b) + (ubase >> 2));
    r.x += bias.x; r.y += bias.y; r.z += bias.z; r.w += bias.w;
    *reinterpret_cast<float4*>(out + (size_t)warp * UNITS + ubase) = r;
}

extern "C" void kernel_launch(void* const* d_in, const int* in_sizes, int n_in,
                              void* d_out, int out_size) {
    const float* vals = (const float*)d_in[0];
    const int*   rows = (const int*)d_in[1];
    const int*   cols = (const int*)d_in[2];
    const float* W    = (const float*)d_in[3];
    const float* b    = (const float*)d_in[4];
    float* out = (float*)d_out;

    int nnz = in_sizes[0];
    int num_rows = out_size / UNITS;

    const int T = 256;
    int n4 = WCOLS * UNITS / 4;   // 262144 float4s of W

    zero_kernel<<<(num_rows + T - 1) / T, T>>>(num_rows);
    scatter_convert_kernel<<<(nnz + T - 1) / T, T>>>(vals, rows, cols, W, nnz, n4);
    int gblocks = (int)(((long)num_rows * 32 + T - 1) / T);
    row_gather_kernel<<<gblocks, T>>>(b, out, num_rows);
}